// round 6
// baseline (speedup 1.0000x reference)
#include <cuda_runtime.h>
#include <cstdint>

#define BB 8
#define NN 2048
#define FF 256
#define ALPHA 0.2f

// Scratch (allocation-free rule: __device__ globals)
__device__ float g_Wh[BB * NN * FF];    // 16 MB fp32 (for compute_s)
__device__ float g_Whr[BB * NN * FF];   // 16 MB tf32-rounded (attn B operand)
__device__ float g_WT[FF * FF];
__device__ float g_s1[BB * NN];
__device__ float g_s2[BB * NN];

__device__ __forceinline__ float to_tf32(float x) {
    uint32_t r; asm("cvt.rna.tf32.f32 %0, %1;" : "=r"(r) : "f"(x));
    return __uint_as_float(r);
}
__device__ __forceinline__ void cp_async16(uint32_t dst, const void* src) {
    asm volatile("cp.async.cg.shared.global [%0], [%1], 16;" :: "r"(dst), "l"(src));
}
#define CP_COMMIT() asm volatile("cp.async.commit_group;" ::: "memory")
#define CP_WAIT0()  asm volatile("cp.async.wait_group 0;" ::: "memory")

// ---------------------------------------------------------------------------
// K0: transpose W
// ---------------------------------------------------------------------------
__global__ void transpose_W(const float* __restrict__ W) {
    __shared__ float tile[32][33];
    int k0 = blockIdx.x * 32;
    int o0 = blockIdx.y * 32;
    int lx = threadIdx.x & 31;
    int ly = threadIdx.x >> 5;
#pragma unroll
    for (int s = 0; s < 32; s += 8)
        tile[ly + s][lx] = W[(o0 + ly + s) * FF + (k0 + lx)];
    __syncthreads();
#pragma unroll
    for (int s = 0; s < 32; s += 8)
        g_WT[(k0 + ly + s) * FF + (o0 + lx)] = tile[lx][ly + s];
}

// ---------------------------------------------------------------------------
// K1: Wh = h @ W^T (fp32); epilogue also writes tf32-rounded g_Whr.
// ---------------------------------------------------------------------------
__global__ __launch_bounds__(256) void gemm_Wh(const float* __restrict__ h) {
    __shared__ float hs[64][32];
    __shared__ float ws[32][256];
    const int row0 = blockIdx.x * 64;
    const int t  = threadIdx.x;
    const int ty = t >> 5, tx = t & 31;
    const int r0 = ty * 8, o0 = tx * 8;

    float acc[8][8];
#pragma unroll
    for (int i = 0; i < 8; i++)
#pragma unroll
        for (int j = 0; j < 8; j++) acc[i][j] = 0.0f;

    for (int k0 = 0; k0 < FF; k0 += 32) {
        {
            float4* dst = (float4*)hs;
#pragma unroll
            for (int s = 0; s < 2; s++) {
                int v = t + 256 * s;
                int row = v >> 3, c = v & 7;
                dst[v] = ((const float4*)(h + (size_t)(row0 + row) * FF + k0))[c];
            }
        }
        {
            float4* dst = (float4*)ws;
#pragma unroll
            for (int s = 0; s < 8; s++) {
                int v = t + 256 * s;
                int kk = v >> 6, c = v & 63;
                dst[v] = ((const float4*)(g_WT + (size_t)(k0 + kk) * FF))[c];
            }
        }
        __syncthreads();

#pragma unroll 8
        for (int kk = 0; kk < 32; kk++) {
            float av[8];
#pragma unroll
            for (int i = 0; i < 8; i++) av[i] = hs[r0 + i][kk];
            float4 w0 = *(const float4*)&ws[kk][o0];
            float4 w1 = *(const float4*)&ws[kk][o0 + 4];
            float bv[8] = {w0.x, w0.y, w0.z, w0.w, w1.x, w1.y, w1.z, w1.w};
#pragma unroll
            for (int i = 0; i < 8; i++)
#pragma unroll
                for (int j = 0; j < 8; j++) acc[i][j] += av[i] * bv[j];
        }
        __syncthreads();
    }

#pragma unroll
    for (int i = 0; i < 8; i++) {
        size_t off = (size_t)(row0 + r0 + i) * FF + o0;
        *(float4*)(g_Wh + off)     = make_float4(acc[i][0], acc[i][1], acc[i][2], acc[i][3]);
        *(float4*)(g_Wh + off + 4) = make_float4(acc[i][4], acc[i][5], acc[i][6], acc[i][7]);
        *(float4*)(g_Whr + off)     = make_float4(to_tf32(acc[i][0]), to_tf32(acc[i][1]),
                                                  to_tf32(acc[i][2]), to_tf32(acc[i][3]));
        *(float4*)(g_Whr + off + 4) = make_float4(to_tf32(acc[i][4]), to_tf32(acc[i][5]),
                                                  to_tf32(acc[i][6]), to_tf32(acc[i][7]));
    }
}

// ---------------------------------------------------------------------------
// K2: s1/s2 row dots (fp32 Wh). One warp per row.
// ---------------------------------------------------------------------------
__global__ void compute_s(const float* __restrict__ a) {
    int gw = (blockIdx.x * blockDim.x + threadIdx.x) >> 5;
    int lane = threadIdx.x & 31;
    if (gw >= BB * NN) return;
    const float4* whr = (const float4*)(g_Wh + (size_t)gw * FF);
    const float4* a1v = (const float4*)a;
    const float4* a2v = ((const float4*)a) + 64;
    float s1 = 0.0f, s2 = 0.0f;
#pragma unroll
    for (int s = 0; s < 2; s++) {
        float4 v  = whr[lane * 2 + s];
        float4 c1 = a1v[lane * 2 + s];
        float4 c2 = a2v[lane * 2 + s];
        s1 += v.x * c1.x + v.y * c1.y + v.z * c1.z + v.w * c1.w;
        s2 += v.x * c2.x + v.y * c2.y + v.z * c2.z + v.w * c2.w;
    }
#pragma unroll
    for (int off = 16; off; off >>= 1) {
        s1 += __shfl_xor_sync(0xffffffffu, s1, off);
        s2 += __shfl_xor_sync(0xffffffffu, s2, off);
    }
    if (lane == 0) { g_s1[gw] = s1; g_s2[gw] = s2; }
}

// ---------------------------------------------------------------------------
// K3: attention. 64 rows x 256 feats per block, j-tiles of 64.
// B-frags: direct LDG from g_Whr (L2), pipelined 1 k-step ahead.
// adj: cp.async double-buffered.  ps: double-buffered.  s2: preloaded.
// smem layout (floats/ints, stride 68 pads):
//   ps  [2][64][68]  34816 B
//   adjs[2][64][68]  34816 B
//   s2a [2048]        8192 B
//   ls  [64]           256 B
// ---------------------------------------------------------------------------
#define PS_STRIDE  68
#define ADJ_STRIDE 68
#define SMEM_PS    0
#define SMEM_ADJ   (2 * 64 * PS_STRIDE * 4)
#define SMEM_S2    (SMEM_ADJ + 2 * 64 * ADJ_STRIDE * 4)
#define SMEM_LS    (SMEM_S2 + NN * 4)
#define SMEM_TOTAL (SMEM_LS + 64 * 4)

__device__ __forceinline__ void mma_tf32(float* d,
                                         uint32_t a0, uint32_t a1, uint32_t a2, uint32_t a3,
                                         uint32_t b0, uint32_t b1) {
    asm volatile("mma.sync.aligned.m16n8k8.row.col.f32.tf32.tf32.f32 "
                 "{%0,%1,%2,%3}, {%4,%5,%6,%7}, {%8,%9}, {%0,%1,%2,%3};"
                 : "+f"(d[0]), "+f"(d[1]), "+f"(d[2]), "+f"(d[3])
                 : "r"(a0), "r"(a1), "r"(a2), "r"(a3), "r"(b0), "r"(b1));
}

__global__ __launch_bounds__(256, 2) void attn(const int* __restrict__ adj,
                                               float* __restrict__ out) {
    extern __shared__ char smem[];
    float* psf  = (float*)(smem + SMEM_PS);     // [buf][row][68]
    int*   adjs = (int*)(smem + SMEM_ADJ);      // [buf][row][68]
    float* s2a  = (float*)(smem + SMEM_S2);
    float* ls   = (float*)(smem + SMEM_LS);
    uint32_t smem_u32;
    { uint64_t tmp; asm("cvta.to.shared.u64 %0, %1;" : "=l"(tmp) : "l"(smem));
      smem_u32 = (uint32_t)tmp; }

    const int b  = blockIdx.y;
    const int i0 = blockIdx.x * 64;
    const int t  = threadIdx.x;
    const int w  = t >> 5;
    const int lane = t & 31;
    const int gid  = lane >> 2;
    const int tig  = lane & 3;
    const int nbase = w * 32;

    // stage-A mapping: 4 threads per row, 16 j's each
    const int arow = t >> 2;
    const int ajl  = (t & 3) * 16;
    const float s1v = g_s1[(size_t)b * NN + i0 + arow];

    // preload s2 for this batch
#pragma unroll
    for (int s = 0; s < 8; s++)
        s2a[t + 256 * s] = g_s2[(size_t)b * NN + t + 256 * s];
    if (t < 64) ls[t] = 0.0f;

    // prefetch adj tile 0 into buf 0
    {
#pragma unroll
        for (int s = 0; s < 4; s++) {
            int v = t + 256 * s;
            int row = v >> 4, c = (v & 15) * 4;
            uint32_t dst = smem_u32 + SMEM_ADJ + (row * ADJ_STRIDE + c) * 4;
            cp_async16(dst, adj + ((size_t)b * NN + i0 + row) * NN + c);
        }
        CP_COMMIT();
    }

    float d[4][4][4];
#pragma unroll
    for (int rg = 0; rg < 4; rg++)
#pragma unroll
        for (int nt = 0; nt < 4; nt++)
#pragma unroll
            for (int c = 0; c < 4; c++) d[rg][nt][c] = 0.0f;

    uint32_t bv[2][4][2];

    for (int tile = 0; tile < NN / 64; tile++) {
        const int j0 = tile * 64;
        const int cur = tile & 1;
        float* psc  = psf + cur * 64 * PS_STRIDE;
        int*   adjc = adjs + cur * 64 * ADJ_STRIDE;

        CP_WAIT0();
        __syncthreads();   // adj(tile) arrived; all warps done with B(tile-1)

        // prefetch adj(tile+1) into the other buffer
        if (tile + 1 < NN / 64) {
#pragma unroll
            for (int s = 0; s < 4; s++) {
                int v = t + 256 * s;
                int row = v >> 4, c = (v & 15) * 4;
                uint32_t dst = smem_u32 + SMEM_ADJ +
                               ((cur ^ 1) * 64 * ADJ_STRIDE + row * ADJ_STRIDE + c) * 4;
                cp_async16(dst, adj + ((size_t)b * NN + i0 + row) * NN + j0 + 64 + c);
            }
            CP_COMMIT();
        }

        // prefetch B-frags for k=0 (independent of stage A)
        const float* wb = g_Whr + ((size_t)b * NN + j0) * FF + nbase + gid;
        {
            const float* p0 = wb + tig * FF;
            const float* p1 = wb + (4 + tig) * FF;
#pragma unroll
            for (int nt = 0; nt < 4; nt++) {
                bv[0][nt][0] = __float_as_uint(__ldg(p0 + nt * 8));
                bv[0][nt][1] = __float_as_uint(__ldg(p1 + nt * 8));
            }
        }

        // ---- stage A: masked tf32 p-tile + exact row sums ----
        {
            const int* arow_p = adjc + arow * ADJ_STRIDE;
            float psum = 0.0f;
#pragma unroll
            for (int q = 0; q < 4; q++) {
                int4 av = *(const int4*)(arow_p + ajl + q * 4);
                int ad[4] = {av.x, av.y, av.z, av.w};
                float pv[4];
#pragma unroll
                for (int s = 0; s < 4; s++) {
                    float x = s1v + s2a[j0 + ajl + q * 4 + s];
                    float e = (x > 0.0f) ? x : ALPHA * x;
                    float p = ad[s] ? __expf(e) : 0.0f;
                    psum += p;
                    pv[s] = to_tf32(p);
                }
                *(float4*)&psc[arow * PS_STRIDE + ajl + q * 4] =
                    make_float4(pv[0], pv[1], pv[2], pv[3]);
            }
            psum += __shfl_xor_sync(0xffffffffu, psum, 1);
            psum += __shfl_xor_sync(0xffffffffu, psum, 2);
            if ((t & 3) == 0) ls[arow] += psum;
        }
        __syncthreads();   // ps ready

        // ---- stage B: tensor-core PV, B-frags pipelined from gmem ----
        const uint32_t* psu = (const uint32_t*)psc;
#pragma unroll
        for (int kk = 0; kk < 8; kk++) {
            const int cb = kk & 1;
            if (kk < 7) {
                const int kn = (kk + 1) * 8;
                const float* p0 = wb + (kn + tig) * FF;
                const float* p1 = wb + (kn + 4 + tig) * FF;
#pragma unroll
                for (int nt = 0; nt < 4; nt++) {
                    bv[cb ^ 1][nt][0] = __float_as_uint(__ldg(p0 + nt * 8));
                    bv[cb ^ 1][nt][1] = __float_as_uint(__ldg(p1 + nt * 8));
                }
            }
            const int k = kk * 8;
#pragma unroll
            for (int rg = 0; rg < 4; rg++) {
                const int ra = rg * 16 + gid;
                uint32_t a0 = psu[ra * PS_STRIDE + k + tig];
                uint32_t a1 = psu[(ra + 8) * PS_STRIDE + k + tig];
                uint32_t a2 = psu[ra * PS_STRIDE + k + 4 + tig];
                uint32_t a3 = psu[(ra + 8) * PS_STRIDE + k + 4 + tig];
#pragma unroll
                for (int nt = 0; nt < 4; nt++)
                    mma_tf32(d[rg][nt], a0, a1, a2, a3, bv[cb][nt][0], bv[cb][nt][1]);
            }
        }
    }

    __syncthreads();   // ls final

    // ---- epilogue ----
#pragma unroll
    for (int rg = 0; rg < 4; rg++) {
        const int ra = rg * 16 + gid;
        float inva = 1.0f / ls[ra];
        float invb = 1.0f / ls[ra + 8];
        float* outa = out + ((size_t)b * NN + i0 + ra) * FF;
        float* outb = outa + (size_t)8 * FF;
#pragma unroll
        for (int nt = 0; nt < 4; nt++) {
            int col = nbase + nt * 8 + 2 * tig;
            *(float2*)(outa + col) = make_float2(d[rg][nt][0] * inva, d[rg][nt][1] * inva);
            *(float2*)(outb + col) = make_float2(d[rg][nt][2] * invb, d[rg][nt][3] * invb);
        }
    }
}

// ---------------------------------------------------------------------------
extern "C" void kernel_launch(void* const* d_in, const int* in_sizes, int n_in,
                              void* d_out, int out_size) {
    const float* h   = (const float*)d_in[0];
    const int*   adj = (const int*)d_in[1];
    const float* W   = (const float*)d_in[2];
    const float* a   = (const float*)d_in[3];
    float* out = (float*)d_out;

    cudaFuncSetAttribute(attn, cudaFuncAttributeMaxDynamicSharedMemorySize, SMEM_TOTAL);

    transpose_W<<<dim3(FF / 32, FF / 32), 256>>>(W);
    gemm_Wh<<<(BB * NN) / 64, 256>>>(h);
    compute_s<<<(BB * NN) / 8, 256>>>(a);
    attn<<<dim3(NN / 64, BB), 256, SMEM_TOTAL>>>(adj, out);
}

// round 8
// speedup vs baseline: 1.1682x; 1.1682x over previous
#include <cuda_runtime.h>
#include <cstdint>

#define BB 8
#define NN 2048
#define FF 256
#define ALPHA 0.2f

// Scratch (allocation-free rule: __device__ globals)
__device__ float g_Wh[BB * NN * FF];    // 16 MB fp32 (for compute_s)
__device__ float g_Whr[BB * NN * FF];   // 16 MB tf32-rounded (attn B operand)
__device__ float g_WT[FF * FF];
__device__ float g_s1[BB * NN];
__device__ float g_s2[BB * NN];

__device__ __forceinline__ float to_tf32(float x) {
    uint32_t r; asm("cvt.rna.tf32.f32 %0, %1;" : "=r"(r) : "f"(x));
    return __uint_as_float(r);
}
__device__ __forceinline__ void cp_async16(uint32_t dst, const void* src) {
    asm volatile("cp.async.cg.shared.global [%0], [%1], 16;" :: "r"(dst), "l"(src));
}
#define CP_COMMIT() asm volatile("cp.async.commit_group;" ::: "memory")
#define CP_WAIT0()  asm volatile("cp.async.wait_group 0;" ::: "memory")

// ---------------------------------------------------------------------------
// K0: transpose W
// ---------------------------------------------------------------------------
__global__ void transpose_W(const float* __restrict__ W) {
    __shared__ float tile[32][33];
    int k0 = blockIdx.x * 32;
    int o0 = blockIdx.y * 32;
    int lx = threadIdx.x & 31;
    int ly = threadIdx.x >> 5;
#pragma unroll
    for (int s = 0; s < 32; s += 8)
        tile[ly + s][lx] = W[(o0 + ly + s) * FF + (k0 + lx)];
    __syncthreads();
#pragma unroll
    for (int s = 0; s < 32; s += 8)
        g_WT[(k0 + ly + s) * FF + (o0 + lx)] = tile[lx][ly + s];
}

// ---------------------------------------------------------------------------
// K1: Wh = h @ W^T (fp32); epilogue also writes tf32-rounded g_Whr.
// ---------------------------------------------------------------------------
__global__ __launch_bounds__(256) void gemm_Wh(const float* __restrict__ h) {
    __shared__ float hs[64][32];
    __shared__ float ws[32][256];
    const int row0 = blockIdx.x * 64;
    const int t  = threadIdx.x;
    const int ty = t >> 5, tx = t & 31;
    const int r0 = ty * 8, o0 = tx * 8;

    float acc[8][8];
#pragma unroll
    for (int i = 0; i < 8; i++)
#pragma unroll
        for (int j = 0; j < 8; j++) acc[i][j] = 0.0f;

    for (int k0 = 0; k0 < FF; k0 += 32) {
        {
            float4* dst = (float4*)hs;
#pragma unroll
            for (int s = 0; s < 2; s++) {
                int v = t + 256 * s;
                int row = v >> 3, c = v & 7;
                dst[v] = ((const float4*)(h + (size_t)(row0 + row) * FF + k0))[c];
            }
        }
        {
            float4* dst = (float4*)ws;
#pragma unroll
            for (int s = 0; s < 8; s++) {
                int v = t + 256 * s;
                int kk = v >> 6, c = v & 63;
                dst[v] = ((const float4*)(g_WT + (size_t)(k0 + kk) * FF))[c];
            }
        }
        __syncthreads();

#pragma unroll 8
        for (int kk = 0; kk < 32; kk++) {
            float av[8];
#pragma unroll
            for (int i = 0; i < 8; i++) av[i] = hs[r0 + i][kk];
            float4 w0 = *(const float4*)&ws[kk][o0];
            float4 w1 = *(const float4*)&ws[kk][o0 + 4];
            float bv[8] = {w0.x, w0.y, w0.z, w0.w, w1.x, w1.y, w1.z, w1.w};
#pragma unroll
            for (int i = 0; i < 8; i++)
#pragma unroll
                for (int j = 0; j < 8; j++) acc[i][j] += av[i] * bv[j];
        }
        __syncthreads();
    }

#pragma unroll
    for (int i = 0; i < 8; i++) {
        size_t off = (size_t)(row0 + r0 + i) * FF + o0;
        *(float4*)(g_Wh + off)     = make_float4(acc[i][0], acc[i][1], acc[i][2], acc[i][3]);
        *(float4*)(g_Wh + off + 4) = make_float4(acc[i][4], acc[i][5], acc[i][6], acc[i][7]);
        *(float4*)(g_Whr + off)     = make_float4(to_tf32(acc[i][0]), to_tf32(acc[i][1]),
                                                  to_tf32(acc[i][2]), to_tf32(acc[i][3]));
        *(float4*)(g_Whr + off + 4) = make_float4(to_tf32(acc[i][4]), to_tf32(acc[i][5]),
                                                  to_tf32(acc[i][6]), to_tf32(acc[i][7]));
    }
}

// ---------------------------------------------------------------------------
// K2: s1/s2 row dots (fp32 Wh). One warp per row.
// ---------------------------------------------------------------------------
__global__ void compute_s(const float* __restrict__ a) {
    int gw = (blockIdx.x * blockDim.x + threadIdx.x) >> 5;
    int lane = threadIdx.x & 31;
    if (gw >= BB * NN) return;
    const float4* whr = (const float4*)(g_Wh + (size_t)gw * FF);
    const float4* a1v = (const float4*)a;
    const float4* a2v = ((const float4*)a) + 64;
    float s1 = 0.0f, s2 = 0.0f;
#pragma unroll
    for (int s = 0; s < 2; s++) {
        float4 v  = whr[lane * 2 + s];
        float4 c1 = a1v[lane * 2 + s];
        float4 c2 = a2v[lane * 2 + s];
        s1 += v.x * c1.x + v.y * c1.y + v.z * c1.z + v.w * c1.w;
        s2 += v.x * c2.x + v.y * c2.y + v.z * c2.z + v.w * c2.w;
    }
#pragma unroll
    for (int off = 16; off; off >>= 1) {
        s1 += __shfl_xor_sync(0xffffffffu, s1, off);
        s2 += __shfl_xor_sync(0xffffffffu, s2, off);
    }
    if (lane == 0) { g_s1[gw] = s1; g_s2[gw] = s2; }
}

// ---------------------------------------------------------------------------
// K3: attention. 64 rows x 256 feats per block, j-tiles of 64.
// whs filled via cp.async from pre-rounded g_Whr, overlapped with stage A.
// adj via direct LDG (front-batched). 2 barriers/tile.
// smem (dynamic):
//   whs : float[64][264]   67584 B
//   ps  : float[64][68]    17408 B
//   s2a : float[2048]       8192 B
//   ls  : float[64]          256 B     total 93440 B -> 2 blocks/SM
// ---------------------------------------------------------------------------
#define WHS_STRIDE 264
#define PS_STRIDE  68
#define SMEM_WHS   0
#define SMEM_PS    (64 * WHS_STRIDE * 4)
#define SMEM_S2    (SMEM_PS + 64 * PS_STRIDE * 4)
#define SMEM_LS    (SMEM_S2 + NN * 4)
#define SMEM_TOTAL (SMEM_LS + 64 * 4)

__device__ __forceinline__ void mma_tf32(float* d,
                                         uint32_t a0, uint32_t a1, uint32_t a2, uint32_t a3,
                                         uint32_t b0, uint32_t b1) {
    asm volatile("mma.sync.aligned.m16n8k8.row.col.f32.tf32.tf32.f32 "
                 "{%0,%1,%2,%3}, {%4,%5,%6,%7}, {%8,%9}, {%0,%1,%2,%3};"
                 : "+f"(d[0]), "+f"(d[1]), "+f"(d[2]), "+f"(d[3])
                 : "r"(a0), "r"(a1), "r"(a2), "r"(a3), "r"(b0), "r"(b1));
}

__global__ __launch_bounds__(256, 2) void attn(const int* __restrict__ adj,
                                               float* __restrict__ out) {
    extern __shared__ char smem[];
    float* psf = (float*)(smem + SMEM_PS);   // [64][68]
    float* s2a = (float*)(smem + SMEM_S2);
    float* ls  = (float*)(smem + SMEM_LS);
    uint32_t smem_u32;
    { uint64_t tmp; asm("cvta.to.shared.u64 %0, %1;" : "=l"(tmp) : "l"(smem));
      smem_u32 = (uint32_t)tmp; }

    const int b  = blockIdx.y;
    const int i0 = blockIdx.x * 64;
    const int t  = threadIdx.x;
    const int w  = t >> 5;
    const int lane = t & 31;
    const int gid  = lane >> 2;
    const int tig  = lane & 3;
    const int nbase = w * 32;

    // stage-A mapping: 4 threads per row, 16 j's each
    const int arow = t >> 2;
    const int ajl  = (t & 3) * 16;
    const float s1v = g_s1[(size_t)b * NN + i0 + arow];
    const int* adjrow = adj + ((size_t)b * NN + i0 + arow) * NN;

    // preload s2 for this batch (covered by first in-loop barrier)
#pragma unroll
    for (int s = 0; s < 8; s++)
        s2a[t + 256 * s] = g_s2[(size_t)b * NN + t + 256 * s];
    if (t < 64) ls[t] = 0.0f;

    float d[4][4][4];
#pragma unroll
    for (int rg = 0; rg < 4; rg++)
#pragma unroll
        for (int nt = 0; nt < 4; nt++)
#pragma unroll
            for (int c = 0; c < 4; c++) d[rg][nt][c] = 0.0f;

    const float* whr_b = g_Whr + (size_t)b * NN * FF;

    for (int tile = 0; tile < NN / 64; tile++) {
        const int j0 = tile * 64;

        __syncthreads();   // stage B(t-1) done: whs + ps free (also covers preloads)

        // ---- issue async whs fill (pre-rounded tf32, no CVT/STS) ----
#pragma unroll
        for (int s = 0; s < 16; s++) {
            int v = t + 256 * s;
            int row = v >> 6, c = (v & 63) * 4;
            cp_async16(smem_u32 + SMEM_WHS + (row * WHS_STRIDE + c) * 4,
                       whr_b + (size_t)(j0 + row) * FF + c);
        }
        CP_COMMIT();

        // ---- stage A (overlaps cp.async flight): front-batched adj LDGs ----
        {
            int4 av[4];
#pragma unroll
            for (int q = 0; q < 4; q++)
                av[q] = *(const int4*)(adjrow + j0 + ajl + q * 4);

            float psum = 0.0f;
#pragma unroll
            for (int q = 0; q < 4; q++) {
                int ad[4] = {av[q].x, av[q].y, av[q].z, av[q].w};
                float pv[4];
#pragma unroll
                for (int s = 0; s < 4; s++) {
                    float x = s1v + s2a[j0 + ajl + q * 4 + s];
                    float e = (x > 0.0f) ? x : ALPHA * x;
                    float p = ad[s] ? __expf(e) : 0.0f;
                    psum += p;
                    pv[s] = to_tf32(p);
                }
                *(float4*)&psf[arow * PS_STRIDE + ajl + q * 4] =
                    make_float4(pv[0], pv[1], pv[2], pv[3]);
            }
            psum += __shfl_xor_sync(0xffffffffu, psum, 1);
            psum += __shfl_xor_sync(0xffffffffu, psum, 2);
            if ((t & 3) == 0) ls[arow] += psum;
        }

        CP_WAIT0();
        __syncthreads();   // whs arrived + ps ready

        // ---- stage B: tensor-core PV from smem (R5-proven) ----
        const uint32_t* psu  = (const uint32_t*)psf;
        const uint32_t* whsu = (const uint32_t*)(smem + SMEM_WHS);
#pragma unroll
        for (int kk = 0; kk < 8; kk++) {
            const int k = kk * 8;
            uint32_t bv[4][2];
            const uint32_t* brow0 = whsu + (k + tig) * WHS_STRIDE + nbase + gid;
            const uint32_t* brow1 = whsu + (k + 4 + tig) * WHS_STRIDE + nbase + gid;
#pragma unroll
            for (int nt = 0; nt < 4; nt++) {
                bv[nt][0] = brow0[nt * 8];
                bv[nt][1] = brow1[nt * 8];
            }
#pragma unroll
            for (int rg = 0; rg < 4; rg++) {
                const int ra = rg * 16 + gid;
                uint32_t a0 = psu[ra * PS_STRIDE + k + tig];
                uint32_t a1 = psu[(ra + 8) * PS_STRIDE + k + tig];
                uint32_t a2 = psu[ra * PS_STRIDE + k + 4 + tig];
                uint32_t a3 = psu[(ra + 8) * PS_STRIDE + k + 4 + tig];
#pragma unroll
                for (int nt = 0; nt < 4; nt++)
                    mma_tf32(d[rg][nt], a0, a1, a2, a3, bv[nt][0], bv[nt][1]);
            }
        }
    }

    // ls last written before the final pre-stage-B barrier -> safe to read
#pragma unroll
    for (int rg = 0; rg < 4; rg++) {
        const int ra = rg * 16 + gid;
        float inva = 1.0f / ls[ra];
        float invb = 1.0f / ls[ra + 8];
        float* outa = out + ((size_t)b * NN + i0 + ra) * FF;
        float* outb = outa + (size_t)8 * FF;
#pragma unroll
        for (int nt = 0; nt < 4; nt++) {
            int col = nbase + nt * 8 + 2 * tig;
            *(float2*)(outa + col) = make_float2(d[rg][nt][0] * inva, d[rg][nt][1] * inva);
            *(float2*)(outb + col) = make_float2(d[rg][nt][2] * invb, d[rg][nt][3] * invb);
        }
    }
}

// ---------------------------------------------------------------------------
extern "C" void kernel_launch(void* const* d_in, const int* in_sizes, int n_in,
                              void* d_out, int out_size) {
    const float* h   = (const float*)d_in[0];
    const int*   adj = (const int*)d_in[1];
    const float* W   = (const float*)d_in[2];
    const float* a   = (const float*)d_in[3];
    float* out = (float*)d_out;

    cudaFuncSetAttribute(attn, cudaFuncAttributeMaxDynamicSharedMemorySize, SMEM_TOTAL);

    transpose_W<<<dim3(FF / 32, FF / 32), 256>>>(W);
    gemm_Wh<<<(BB * NN) / 64, 256>>>(h);
    compute_s<<<(BB * NN) / 8, 256>>>(a);
    attn<<<dim3(NN / 64, BB), 256, SMEM_TOTAL>>>(adj, out);
}

// round 11
// speedup vs baseline: 1.2412x; 1.0625x over previous
#include <cuda_runtime.h>
#include <cstdint>

#define BB 8
#define NN 2048
#define FF 256
#define ALPHA 0.2f
#define JT 32
#define NT (NN / JT)

// Scratch (allocation-free rule: __device__ globals)
__device__ float g_Wh[BB * NN * FF];    // fp32 (for compute_s)
__device__ float g_Whr[BB * NN * FF];   // tf32-rounded (attn B operand)
__device__ float g_WT[FF * FF];
__device__ float g_s1[BB * NN];
__device__ float g_s2[BB * NN];

__device__ __forceinline__ float to_tf32(float x) {
    uint32_t r; asm("cvt.rna.tf32.f32 %0, %1;" : "=r"(r) : "f"(x));
    return __uint_as_float(r);
}
__device__ __forceinline__ void cp_async16(uint32_t dst, const void* src) {
    asm volatile("cp.async.cg.shared.global [%0], [%1], 16;" :: "r"(dst), "l"(src));
}
#define CP_COMMIT() asm volatile("cp.async.commit_group;" ::: "memory")
#define CP_WAIT0()  asm volatile("cp.async.wait_group 0;" ::: "memory")
#define CP_WAIT1()  asm volatile("cp.async.wait_group 1;" ::: "memory")

// ---------------------------------------------------------------------------
// K0: transpose W
// ---------------------------------------------------------------------------
__global__ void transpose_W(const float* __restrict__ W) {
    __shared__ float tile[32][33];
    int k0 = blockIdx.x * 32;
    int o0 = blockIdx.y * 32;
    int lx = threadIdx.x & 31;
    int ly = threadIdx.x >> 5;
#pragma unroll
    for (int s = 0; s < 32; s += 8)
        tile[ly + s][lx] = W[(o0 + ly + s) * FF + (k0 + lx)];
    __syncthreads();
#pragma unroll
    for (int s = 0; s < 32; s += 8)
        g_WT[(k0 + ly + s) * FF + (o0 + lx)] = tile[lx][ly + s];
}

// ---------------------------------------------------------------------------
// K1: Wh = h @ W^T (fp32); epilogue also writes tf32-rounded g_Whr.
// ---------------------------------------------------------------------------
__global__ __launch_bounds__(256) void gemm_Wh(const float* __restrict__ h) {
    __shared__ float hs[64][32];
    __shared__ float ws[32][256];
    const int row0 = blockIdx.x * 64;
    const int t  = threadIdx.x;
    const int ty = t >> 5, tx = t & 31;
    const int r0 = ty * 8, o0 = tx * 8;

    float acc[8][8];
#pragma unroll
    for (int i = 0; i < 8; i++)
#pragma unroll
        for (int j = 0; j < 8; j++) acc[i][j] = 0.0f;

    for (int k0 = 0; k0 < FF; k0 += 32) {
        {
            float4* dst = (float4*)hs;
#pragma unroll
            for (int s = 0; s < 2; s++) {
                int v = t + 256 * s;
                int row = v >> 3, c = v & 7;
                dst[v] = ((const float4*)(h + (size_t)(row0 + row) * FF + k0))[c];
            }
        }
        {
            float4* dst = (float4*)ws;
#pragma unroll
            for (int s = 0; s < 8; s++) {
                int v = t + 256 * s;
                int kk = v >> 6, c = v & 63;
                dst[v] = ((const float4*)(g_WT + (size_t)(k0 + kk) * FF))[c];
            }
        }
        __syncthreads();

#pragma unroll 8
        for (int kk = 0; kk < 32; kk++) {
            float av[8];
#pragma unroll
            for (int i = 0; i < 8; i++) av[i] = hs[r0 + i][kk];
            float4 w0 = *(const float4*)&ws[kk][o0];
            float4 w1 = *(const float4*)&ws[kk][o0 + 4];
            float bv[8] = {w0.x, w0.y, w0.z, w0.w, w1.x, w1.y, w1.z, w1.w};
#pragma unroll
            for (int i = 0; i < 8; i++)
#pragma unroll
                for (int j = 0; j < 8; j++) acc[i][j] += av[i] * bv[j];
        }
        __syncthreads();
    }

#pragma unroll
    for (int i = 0; i < 8; i++) {
        size_t off = (size_t)(row0 + r0 + i) * FF + o0;
        *(float4*)(g_Wh + off)     = make_float4(acc[i][0], acc[i][1], acc[i][2], acc[i][3]);
        *(float4*)(g_Wh + off + 4) = make_float4(acc[i][4], acc[i][5], acc[i][6], acc[i][7]);
        *(float4*)(g_Whr + off)     = make_float4(to_tf32(acc[i][0]), to_tf32(acc[i][1]),
                                                  to_tf32(acc[i][2]), to_tf32(acc[i][3]));
        *(float4*)(g_Whr + off + 4) = make_float4(to_tf32(acc[i][4]), to_tf32(acc[i][5]),
                                                  to_tf32(acc[i][6]), to_tf32(acc[i][7]));
    }
}

// ---------------------------------------------------------------------------
// K2: s1/s2 row dots (fp32 Wh). One warp per row.
// ---------------------------------------------------------------------------
__global__ void compute_s(const float* __restrict__ a) {
    int gw = (blockIdx.x * blockDim.x + threadIdx.x) >> 5;
    int lane = threadIdx.x & 31;
    if (gw >= BB * NN) return;
    const float4* whr = (const float4*)(g_Wh + (size_t)gw * FF);
    const float4* a1v = (const float4*)a;
    const float4* a2v = ((const float4*)a) + 64;
    float s1 = 0.0f, s2 = 0.0f;
#pragma unroll
    for (int s = 0; s < 2; s++) {
        float4 v  = whr[lane * 2 + s];
        float4 c1 = a1v[lane * 2 + s];
        float4 c2 = a2v[lane * 2 + s];
        s1 += v.x * c1.x + v.y * c1.y + v.z * c1.z + v.w * c1.w;
        s2 += v.x * c2.x + v.y * c2.y + v.z * c2.z + v.w * c2.w;
    }
#pragma unroll
    for (int off = 16; off; off >>= 1) {
        s1 += __shfl_xor_sync(0xffffffffu, s1, off);
        s2 += __shfl_xor_sync(0xffffffffu, s2, off);
    }
    if (lane == 0) { g_s1[gw] = s1; g_s2[gw] = s2; }
}

// ---------------------------------------------------------------------------
// K3: attention, pipelined at R8's proven shape: 256 threads, 64 rows x 256 f,
// 2 blocks/SM. j-tiles of 32, double-buffered whs (cp.async) + ps,
// front-batched adj LDGs, 1 barrier per tile.
// smem (dynamic):
//   whs[2] : float[32][264]   67584 B
//   ps [2] : float[64][36]    18432 B
//   s2a    : float[2048]       8192 B
//   ls     : float[64]          256 B     total 94464 B -> 2 blocks/SM
// ---------------------------------------------------------------------------
#define WHS_STRIDE 264
#define PS_STRIDE  36
#define WHS_BYTES  (JT * WHS_STRIDE * 4)
#define PS_BYTES   (64 * PS_STRIDE * 4)
#define SMEM_WHS   0
#define SMEM_PS    (2 * WHS_BYTES)
#define SMEM_S2    (SMEM_PS + 2 * PS_BYTES)
#define SMEM_LS    (SMEM_S2 + NN * 4)
#define SMEM_TOTAL (SMEM_LS + 64 * 4)

__device__ __forceinline__ void mma_tf32(float* d,
                                         uint32_t a0, uint32_t a1, uint32_t a2, uint32_t a3,
                                         uint32_t b0, uint32_t b1) {
    asm volatile("mma.sync.aligned.m16n8k8.row.col.f32.tf32.tf32.f32 "
                 "{%0,%1,%2,%3}, {%4,%5,%6,%7}, {%8,%9}, {%0,%1,%2,%3};"
                 : "+f"(d[0]), "+f"(d[1]), "+f"(d[2]), "+f"(d[3])
                 : "r"(a0), "r"(a1), "r"(a2), "r"(a3), "r"(b0), "r"(b1));
}

__global__ __launch_bounds__(256, 2) void attn(const int* __restrict__ adj,
                                               float* __restrict__ out) {
    extern __shared__ char smem[];
    float* s2a = (float*)(smem + SMEM_S2);
    float* ls  = (float*)(smem + SMEM_LS);
    uint32_t smem_u32;
    { uint64_t tmp; asm("cvta.to.shared.u64 %0, %1;" : "=l"(tmp) : "l"(smem));
      smem_u32 = (uint32_t)tmp; }

    const int b  = blockIdx.y;
    const int i0 = blockIdx.x * 64;
    const int t  = threadIdx.x;
    const int w  = t >> 5;
    const int lane = t & 31;
    const int gid  = lane >> 2;
    const int tig  = lane & 3;
    const int nbase = w * 32;        // 8 warps = 8 feat groups of 32 cols

    // stage-A mapping: 4 threads per row, 8 j's each (64 rows, JT=32)
    const int arow = t >> 2;
    const int ajl  = (t & 3) * 8;
    const float s1v = g_s1[(size_t)b * NN + i0 + arow];
    const int* adjrow = adj + ((size_t)b * NN + i0 + arow) * NN;
    const float* whr_b = g_Whr + (size_t)b * NN * FF;

    // preload s2 (512 float4, 2 per thread) + ls init
    ((float4*)s2a)[t]       = ((const float4*)(g_s2 + (size_t)b * NN))[t];
    ((float4*)s2a)[t + 256] = ((const float4*)(g_s2 + (size_t)b * NN))[t + 256];
    if (t < 64) ls[t] = 0.0f;

    float d[4][4][4];
#pragma unroll
    for (int rg = 0; rg < 4; rg++)
#pragma unroll
        for (int nt = 0; nt < 4; nt++)
#pragma unroll
            for (int c = 0; c < 4; c++) d[rg][nt][c] = 0.0f;

    // ---- prologue: issue whs(0) + adj(0); A(0) after barrier ----
    {
#pragma unroll
        for (int s = 0; s < 8; s++) {
            int v = t + 256 * s;               // 2048 float4 = 32 rows x 64 c4
            int row = v >> 6, c = (v & 63) * 4;
            cp_async16(smem_u32 + SMEM_WHS + (row * WHS_STRIDE + c) * 4,
                       whr_b + (size_t)row * FF + c);
        }
        CP_COMMIT();
    }
    int4 av[2];
#pragma unroll
    for (int q = 0; q < 2; q++) av[q] = *(const int4*)(adjrow + ajl + q * 4);
    __syncthreads();   // s2a / ls visible

    // stage A(0) -> ps buf 0
    {
        float* psc = (float*)(smem + SMEM_PS);
        float psum = 0.0f;
#pragma unroll
        for (int q = 0; q < 2; q++) {
            int ad[4] = {av[q].x, av[q].y, av[q].z, av[q].w};
            float pv[4];
#pragma unroll
            for (int s = 0; s < 4; s++) {
                float x = s1v + s2a[ajl + q * 4 + s];
                float e = (x > 0.0f) ? x : ALPHA * x;
                float p = ad[s] ? __expf(e) : 0.0f;
                psum += p;
                pv[s] = to_tf32(p);
            }
            *(float4*)&psc[arow * PS_STRIDE + ajl + q * 4] =
                make_float4(pv[0], pv[1], pv[2], pv[3]);
        }
        psum += __shfl_xor_sync(0xffffffffu, psum, 1);
        psum += __shfl_xor_sync(0xffffffffu, psum, 2);
        if ((t & 3) == 0) ls[arow] += psum;
    }

    // ---- main loop: 1 barrier per tile ----
    for (int tile = 0; tile < NT; tile++) {
        const int cur = tile & 1;

        __syncthreads();   // A(tile) ps visible; B(tile-1) done with old bufs

        const bool more = (tile + 1 < NT);
        if (more) {
            const int jn = (tile + 1) * JT;
            // issue whs(tile+1) into the other buffer
#pragma unroll
            for (int s = 0; s < 8; s++) {
                int v = t + 256 * s;
                int row = v >> 6, c = (v & 63) * 4;
                cp_async16(smem_u32 + SMEM_WHS + (cur ^ 1) * WHS_BYTES +
                               (row * WHS_STRIDE + c) * 4,
                           whr_b + (size_t)(jn + row) * FF + c);
            }
            CP_COMMIT();
            // front-batch adj(tile+1) LDGs (consumed after stage B)
#pragma unroll
            for (int q = 0; q < 2; q++)
                av[q] = *(const int4*)(adjrow + jn + ajl + q * 4);
            CP_WAIT1();    // whs(tile) arrived (committed one iteration ago)
        } else {
            CP_WAIT0();
        }

        // ---- stage B(tile): tensor-core PV ----
        const uint32_t* psu  = (const uint32_t*)(smem + SMEM_PS + cur * PS_BYTES);
        const uint32_t* whsu = (const uint32_t*)(smem + SMEM_WHS + cur * WHS_BYTES);
#pragma unroll
        for (int kk = 0; kk < 4; kk++) {
            const int k = kk * 8;
            uint32_t bv[4][2];
            const uint32_t* brow0 = whsu + (k + tig) * WHS_STRIDE + nbase + gid;
            const uint32_t* brow1 = whsu + (k + 4 + tig) * WHS_STRIDE + nbase + gid;
#pragma unroll
            for (int nt = 0; nt < 4; nt++) {
                bv[nt][0] = brow0[nt * 8];
                bv[nt][1] = brow1[nt * 8];
            }
#pragma unroll
            for (int rg = 0; rg < 4; rg++) {
                const int ra = rg * 16 + gid;
                uint32_t a0 = psu[ra * PS_STRIDE + k + tig];
                uint32_t a1 = psu[(ra + 8) * PS_STRIDE + k + tig];
                uint32_t a2 = psu[ra * PS_STRIDE + k + 4 + tig];
                uint32_t a3 = psu[(ra + 8) * PS_STRIDE + k + 4 + tig];
#pragma unroll
                for (int nt = 0; nt < 4; nt++)
                    mma_tf32(d[rg][nt], a0, a1, a2, a3, bv[nt][0], bv[nt][1]);
            }
        }

        // ---- stage A(tile+1): adj regs arrived during MMAs ----
        if (more) {
            const int jn = (tile + 1) * JT;
            float* psc = (float*)(smem + SMEM_PS + (cur ^ 1) * PS_BYTES);
            float psum = 0.0f;
#pragma unroll
            for (int q = 0; q < 2; q++) {
                int ad[4] = {av[q].x, av[q].y, av[q].z, av[q].w};
                float pv[4];
#pragma unroll
                for (int s = 0; s < 4; s++) {
                    float x = s1v + s2a[jn + ajl + q * 4 + s];
                    float e = (x > 0.0f) ? x : ALPHA * x;
                    float p = ad[s] ? __expf(e) : 0.0f;
                    psum += p;
                    pv[s] = to_tf32(p);
                }
                *(float4*)&psc[arow * PS_STRIDE + ajl + q * 4] =
                    make_float4(pv[0], pv[1], pv[2], pv[3]);
            }
            psum += __shfl_xor_sync(0xffffffffu, psum, 1);
            psum += __shfl_xor_sync(0xffffffffu, psum, 2);
            if ((t & 3) == 0) ls[arow] += psum;
        }
    }

    __syncthreads();   // all ls updates visible

    // ---- epilogue: divide by row sums, store ----
#pragma unroll
    for (int rg = 0; rg < 4; rg++) {
        const int ra = rg * 16 + gid;
        float inva = 1.0f / ls[ra];
        float invb = 1.0f / ls[ra + 8];
        float* outa = out + ((size_t)b * NN + i0 + ra) * FF;
        float* outb = outa + (size_t)8 * FF;
#pragma unroll
        for (int nt = 0; nt < 4; nt++) {
            int col = nbase + nt * 8 + 2 * tig;
            *(float2*)(outa + col) = make_float2(d[rg][nt][0] * inva, d[rg][nt][1] * inva);
            *(float2*)(outb + col) = make_float2(d[rg][nt][2] * invb, d[rg][nt][3] * invb);
        }
    }
}

// ---------------------------------------------------------------------------
extern "C" void kernel_launch(void* const* d_in, const int* in_sizes, int n_in,
                              void* d_out, int out_size) {
    const float* h   = (const float*)d_in[0];
    const int*   adj = (const int*)d_in[1];
    const float* W   = (const float*)d_in[2];
    const float* a   = (const float*)d_in[3];
    float* out = (float*)d_out;

    cudaFuncSetAttribute(attn, cudaFuncAttributeMaxDynamicSharedMemorySize, SMEM_TOTAL);

    transpose_W<<<dim3(FF / 32, FF / 32), 256>>>(W);
    gemm_Wh<<<(BB * NN) / 64, 256>>>(h);
    compute_s<<<(BB * NN) / 8, 256>>>(a);
    attn<<<dim3(NN / 64, BB), 256, SMEM_TOTAL>>>(adj, out);
}

// round 15
// speedup vs baseline: 1.5812x; 1.2739x over previous
#include <cuda_runtime.h>
#include <cstdint>

#define BB 8
#define NN 2048
#define FF 256
#define ALPHA 0.2f
#define JT 32
#define NT (NN / JT)

// Scratch (allocation-free rule: __device__ globals)
__device__ float g_Whr[BB * NN * FF];   // tf32-rounded Wh (attn B operand)
__device__ float g_WT[FF * FF];         // W transposed [k][o]
__device__ float g_s1[BB * NN];
__device__ float g_s2[BB * NN];

__device__ __forceinline__ float to_tf32(float x) {
    uint32_t r; asm("cvt.rna.tf32.f32 %0, %1;" : "=r"(r) : "f"(x));
    return __uint_as_float(r);
}
__device__ __forceinline__ void cp_async16(uint32_t dst, const void* src) {
    asm volatile("cp.async.cg.shared.global [%0], [%1], 16;" :: "r"(dst), "l"(src));
}
#define CP_COMMIT() asm volatile("cp.async.commit_group;" ::: "memory")
#define CP_WAIT0()  asm volatile("cp.async.wait_group 0;" ::: "memory")
#define CP_WAIT1()  asm volatile("cp.async.wait_group 1;" ::: "memory")

__device__ __forceinline__ void mma_tf32(float* d,
                                         uint32_t a0, uint32_t a1, uint32_t a2, uint32_t a3,
                                         uint32_t b0, uint32_t b1) {
    asm volatile("mma.sync.aligned.m16n8k8.row.col.f32.tf32.tf32.f32 "
                 "{%0,%1,%2,%3}, {%4,%5,%6,%7}, {%8,%9}, {%0,%1,%2,%3};"
                 : "+f"(d[0]), "+f"(d[1]), "+f"(d[2]), "+f"(d[3])
                 : "r"(a0), "r"(a1), "r"(a2), "r"(a3), "r"(b0), "r"(b1));
}

// ---------------------------------------------------------------------------
// K0: transpose W [F_OUT, F_IN] -> g_WT [F_IN, F_OUT]
// ---------------------------------------------------------------------------
__global__ void transpose_W(const float* __restrict__ W) {
    __shared__ float tile[32][33];
    int k0 = blockIdx.x * 32;
    int o0 = blockIdx.y * 32;
    int lx = threadIdx.x & 31;
    int ly = threadIdx.x >> 5;
#pragma unroll
    for (int s = 0; s < 32; s += 8)
        tile[ly + s][lx] = W[(o0 + ly + s) * FF + (k0 + lx)];
    __syncthreads();
#pragma unroll
    for (int s = 0; s < 32; s += 8)
        g_WT[(k0 + ly + s) * FF + (o0 + lx)] = tile[lx][ly + s];
}

// ---------------------------------------------------------------------------
// K1: Wh = h @ W^T via tf32 mma.sync (fragment mapping identical to attn
// stage B, proven in R11). Epilogue: writes tf32-rounded g_Whr AND fused
// s1/s2 row dots (shfl-reduce over tig, smem atomicAdd across warps).
// Block: 64 rows x 256 outs, 8 warps = 8 col-groups of 32.
// smem: hs[64][36] 9216 B, ws[32][264] 33792 B, s1s/s2s 512 B.
// ---------------------------------------------------------------------------
#define HS_STRIDE 36
#define WS_STRIDE 264

__global__ __launch_bounds__(256) void gemm_Wh(const float* __restrict__ h,
                                               const float* __restrict__ a) {
    __shared__ float hs[64 * HS_STRIDE];
    __shared__ float ws[32 * WS_STRIDE];
    __shared__ float s1s[64], s2s[64];
    const int row0 = blockIdx.x * 64;
    const int t = threadIdx.x;
    const int w = t >> 5;
    const int lane = t & 31;
    const int gid = lane >> 2, tig = lane & 3;
    const int nbase = w * 32;

    if (t < 64) { s1s[t] = 0.0f; s2s[t] = 0.0f; }

    float d[4][4][4];
#pragma unroll
    for (int rg = 0; rg < 4; rg++)
#pragma unroll
        for (int nt = 0; nt < 4; nt++)
#pragma unroll
            for (int c = 0; c < 4; c++) d[rg][nt][c] = 0.0f;

    for (int kt = 0; kt < 8; kt++) {
        __syncthreads();   // previous MMA pass done (also covers s1s init)
        // fill hs (tf32-rounded): 64 rows x 32 k
#pragma unroll
        for (int s = 0; s < 2; s++) {
            int v = t + 256 * s;
            int row = v >> 3, c4 = v & 7;
            float4 x = *(const float4*)(h + (size_t)(row0 + row) * FF + kt * 32 + c4 * 4);
            x.x = to_tf32(x.x); x.y = to_tf32(x.y);
            x.z = to_tf32(x.z); x.w = to_tf32(x.w);
            *(float4*)&hs[row * HS_STRIDE + c4 * 4] = x;
        }
        // fill ws (tf32-rounded): 32 k x 256 o
#pragma unroll
        for (int s = 0; s < 8; s++) {
            int v = t + 256 * s;
            int kk = v >> 6, c4 = v & 63;
            float4 x = *(const float4*)(g_WT + (size_t)(kt * 32 + kk) * FF + c4 * 4);
            x.x = to_tf32(x.x); x.y = to_tf32(x.y);
            x.z = to_tf32(x.z); x.w = to_tf32(x.w);
            *(float4*)&ws[kk * WS_STRIDE + c4 * 4] = x;
        }
        __syncthreads();

        const uint32_t* hsu = (const uint32_t*)hs;
        const uint32_t* wsu = (const uint32_t*)ws;
#pragma unroll
        for (int kk = 0; kk < 4; kk++) {
            const int k = kk * 8;
            uint32_t bv[4][2];
            const uint32_t* brow0 = wsu + (k + tig) * WS_STRIDE + nbase + gid;
            const uint32_t* brow1 = wsu + (k + 4 + tig) * WS_STRIDE + nbase + gid;
#pragma unroll
            for (int nt = 0; nt < 4; nt++) {
                bv[nt][0] = brow0[nt * 8];
                bv[nt][1] = brow1[nt * 8];
            }
#pragma unroll
            for (int rg = 0; rg < 4; rg++) {
                const int ra = rg * 16 + gid;
                uint32_t a0 = hsu[ra * HS_STRIDE + k + tig];
                uint32_t a1 = hsu[(ra + 8) * HS_STRIDE + k + tig];
                uint32_t a2 = hsu[ra * HS_STRIDE + k + 4 + tig];
                uint32_t a3 = hsu[(ra + 8) * HS_STRIDE + k + 4 + tig];
#pragma unroll
                for (int nt = 0; nt < 4; nt++)
                    mma_tf32(d[rg][nt], a0, a1, a2, a3, bv[nt][0], bv[nt][1]);
            }
        }
    }

    // ---- epilogue: Whr (tf32-rounded) + fused s1/s2 partial dots ----
#pragma unroll
    for (int rg = 0; rg < 4; rg++) {
        const int ra = rg * 16 + gid;
        float p1A = 0.0f, p2A = 0.0f, p1B = 0.0f, p2B = 0.0f;
#pragma unroll
        for (int nt = 0; nt < 4; nt++) {
            int col = nbase + nt * 8 + 2 * tig;
            float a10 = a[col], a11 = a[col + 1];
            float a20 = a[FF + col], a21 = a[FF + col + 1];
            p1A += d[rg][nt][0] * a10 + d[rg][nt][1] * a11;
            p2A += d[rg][nt][0] * a20 + d[rg][nt][1] * a21;
            p1B += d[rg][nt][2] * a10 + d[rg][nt][3] * a11;
            p2B += d[rg][nt][2] * a20 + d[rg][nt][3] * a21;
            *(float2*)(g_Whr + (size_t)(row0 + ra) * FF + col) =
                make_float2(to_tf32(d[rg][nt][0]), to_tf32(d[rg][nt][1]));
            *(float2*)(g_Whr + (size_t)(row0 + ra + 8) * FF + col) =
                make_float2(to_tf32(d[rg][nt][2]), to_tf32(d[rg][nt][3]));
        }
        // reduce over tig (lanes differing in bits 0..1)
        p1A += __shfl_xor_sync(0xffffffffu, p1A, 1);
        p1A += __shfl_xor_sync(0xffffffffu, p1A, 2);
        p2A += __shfl_xor_sync(0xffffffffu, p2A, 1);
        p2A += __shfl_xor_sync(0xffffffffu, p2A, 2);
        p1B += __shfl_xor_sync(0xffffffffu, p1B, 1);
        p1B += __shfl_xor_sync(0xffffffffu, p1B, 2);
        p2B += __shfl_xor_sync(0xffffffffu, p2B, 1);
        p2B += __shfl_xor_sync(0xffffffffu, p2B, 2);
        if (tig == 0) {
            atomicAdd(&s1s[ra], p1A);
            atomicAdd(&s2s[ra], p2A);
            atomicAdd(&s1s[ra + 8], p1B);
            atomicAdd(&s2s[ra + 8], p2B);
        }
    }
    __syncthreads();
    if (t < 64) {
        g_s1[row0 + t] = s1s[t];
        g_s2[row0 + t] = s2s[t];
    }
}

// ---------------------------------------------------------------------------
// K3: attention — byte-identical to R11 (proven 158.7 us).
// 256 threads, 64 rows x 256 f, 2 blocks/SM. j-tiles of 32, double-buffered
// whs (cp.async) + ps, front-batched adj LDGs, 1 barrier per tile.
// ---------------------------------------------------------------------------
#define WHS_STRIDE 264
#define PS_STRIDE  36
#define WHS_BYTES  (JT * WHS_STRIDE * 4)
#define PS_BYTES   (64 * PS_STRIDE * 4)
#define SMEM_WHS   0
#define SMEM_PS    (2 * WHS_BYTES)
#define SMEM_S2    (SMEM_PS + 2 * PS_BYTES)
#define SMEM_LS    (SMEM_S2 + NN * 4)
#define SMEM_TOTAL (SMEM_LS + 64 * 4)

__global__ __launch_bounds__(256, 2) void attn(const int* __restrict__ adj,
                                               float* __restrict__ out) {
    extern __shared__ char smem[];
    float* s2a = (float*)(smem + SMEM_S2);
    float* ls  = (float*)(smem + SMEM_LS);
    uint32_t smem_u32;
    { uint64_t tmp; asm("cvta.to.shared.u64 %0, %1;" : "=l"(tmp) : "l"(smem));
      smem_u32 = (uint32_t)tmp; }

    const int b  = blockIdx.y;
    const int i0 = blockIdx.x * 64;
    const int t  = threadIdx.x;
    const int w  = t >> 5;
    const int lane = t & 31;
    const int gid  = lane >> 2;
    const int tig  = lane & 3;
    const int nbase = w * 32;

    const int arow = t >> 2;
    const int ajl  = (t & 3) * 8;
    const float s1v = g_s1[(size_t)b * NN + i0 + arow];
    const int* adjrow = adj + ((size_t)b * NN + i0 + arow) * NN;
    const float* whr_b = g_Whr + (size_t)b * NN * FF;

    ((float4*)s2a)[t]       = ((const float4*)(g_s2 + (size_t)b * NN))[t];
    ((float4*)s2a)[t + 256] = ((const float4*)(g_s2 + (size_t)b * NN))[t + 256];
    if (t < 64) ls[t] = 0.0f;

    float d[4][4][4];
#pragma unroll
    for (int rg = 0; rg < 4; rg++)
#pragma unroll
        for (int nt = 0; nt < 4; nt++)
#pragma unroll
            for (int c = 0; c < 4; c++) d[rg][nt][c] = 0.0f;

    // ---- prologue: issue whs(0) + adj(0); A(0) after barrier ----
    {
#pragma unroll
        for (int s = 0; s < 8; s++) {
            int v = t + 256 * s;
            int row = v >> 6, c = (v & 63) * 4;
            cp_async16(smem_u32 + SMEM_WHS + (row * WHS_STRIDE + c) * 4,
                       whr_b + (size_t)row * FF + c);
        }
        CP_COMMIT();
    }
    int4 av[2];
#pragma unroll
    for (int q = 0; q < 2; q++) av[q] = *(const int4*)(adjrow + ajl + q * 4);
    __syncthreads();

    {
        float* psc = (float*)(smem + SMEM_PS);
        float psum = 0.0f;
#pragma unroll
        for (int q = 0; q < 2; q++) {
            int ad[4] = {av[q].x, av[q].y, av[q].z, av[q].w};
            float pv[4];
#pragma unroll
            for (int s = 0; s < 4; s++) {
                float x = s1v + s2a[ajl + q * 4 + s];
                float e = (x > 0.0f) ? x : ALPHA * x;
                float p = ad[s] ? __expf(e) : 0.0f;
                psum += p;
                pv[s] = to_tf32(p);
            }
            *(float4*)&psc[arow * PS_STRIDE + ajl + q * 4] =
                make_float4(pv[0], pv[1], pv[2], pv[3]);
        }
        psum += __shfl_xor_sync(0xffffffffu, psum, 1);
        psum += __shfl_xor_sync(0xffffffffu, psum, 2);
        if ((t & 3) == 0) ls[arow] += psum;
    }

    for (int tile = 0; tile < NT; tile++) {
        const int cur = tile & 1;

        __syncthreads();

        const bool more = (tile + 1 < NT);
        if (more) {
            const int jn = (tile + 1) * JT;
#pragma unroll
            for (int s = 0; s < 8; s++) {
                int v = t + 256 * s;
                int row = v >> 6, c = (v & 63) * 4;
                cp_async16(smem_u32 + SMEM_WHS + (cur ^ 1) * WHS_BYTES +
                               (row * WHS_STRIDE + c) * 4,
                           whr_b + (size_t)(jn + row) * FF + c);
            }
            CP_COMMIT();
#pragma unroll
            for (int q = 0; q < 2; q++)
                av[q] = *(const int4*)(adjrow + jn + ajl + q * 4);
            CP_WAIT1();
        } else {
            CP_WAIT0();
        }

        const uint32_t* psu  = (const uint32_t*)(smem + SMEM_PS + cur * PS_BYTES);
        const uint32_t* whsu = (const uint32_t*)(smem + SMEM_WHS + cur * WHS_BYTES);
#pragma unroll
        for (int kk = 0; kk < 4; kk++) {
            const int k = kk * 8;
            uint32_t bv[4][2];
            const uint32_t* brow0 = whsu + (k + tig) * WHS_STRIDE + nbase + gid;
            const uint32_t* brow1 = whsu + (k + 4 + tig) * WHS_STRIDE + nbase + gid;
#pragma unroll
            for (int nt = 0; nt < 4; nt++) {
                bv[nt][0] = brow0[nt * 8];
                bv[nt][1] = brow1[nt * 8];
            }
#pragma unroll
            for (int rg = 0; rg < 4; rg++) {
                const int ra = rg * 16 + gid;
                uint32_t a0 = psu[ra * PS_STRIDE + k + tig];
                uint32_t a1 = psu[(ra + 8) * PS_STRIDE + k + tig];
                uint32_t a2 = psu[ra * PS_STRIDE + k + 4 + tig];
                uint32_t a3 = psu[(ra + 8) * PS_STRIDE + k + 4 + tig];
#pragma unroll
                for (int nt = 0; nt < 4; nt++)
                    mma_tf32(d[rg][nt], a0, a1, a2, a3, bv[nt][0], bv[nt][1]);
            }
        }

        if (more) {
            const int jn = (tile + 1) * JT;
            float* psc = (float*)(smem + SMEM_PS + (cur ^ 1) * PS_BYTES);
            float psum = 0.0f;
#pragma unroll
            for (int q = 0; q < 2; q++) {
                int ad[4] = {av[q].x, av[q].y, av[q].z, av[q].w};
                float pv[4];
#pragma unroll
                for (int s = 0; s < 4; s++) {
                    float x = s1v + s2a[jn + ajl + q * 4 + s];
                    float e = (x > 0.0f) ? x : ALPHA * x;
                    float p = ad[s] ? __expf(e) : 0.0f;
                    psum += p;
                    pv[s] = to_tf32(p);
                }
                *(float4*)&psc[arow * PS_STRIDE + ajl + q * 4] =
                    make_float4(pv[0], pv[1], pv[2], pv[3]);
            }
            psum += __shfl_xor_sync(0xffffffffu, psum, 1);
            psum += __shfl_xor_sync(0xffffffffu, psum, 2);
            if ((t & 3) == 0) ls[arow] += psum;
        }
    }

    __syncthreads();

#pragma unroll
    for (int rg = 0; rg < 4; rg++) {
        const int ra = rg * 16 + gid;
        float inva = 1.0f / ls[ra];
        float invb = 1.0f / ls[ra + 8];
        float* outa = out + ((size_t)b * NN + i0 + ra) * FF;
        float* outb = outa + (size_t)8 * FF;
#pragma unroll
        for (int nt = 0; nt < 4; nt++) {
            int col = nbase + nt * 8 + 2 * tig;
            *(float2*)(outa + col) = make_float2(d[rg][nt][0] * inva, d[rg][nt][1] * inva);
            *(float2*)(outb + col) = make_float2(d[rg][nt][2] * invb, d[rg][nt][3] * invb);
        }
    }
}

// ---------------------------------------------------------------------------
extern "C" void kernel_launch(void* const* d_in, const int* in_sizes, int n_in,
                              void* d_out, int out_size) {
    const float* h   = (const float*)d_in[0];
    const int*   adj = (const int*)d_in[1];
    const float* W   = (const float*)d_in[2];
    const float* a   = (const float*)d_in[3];
    float* out = (float*)d_out;

    cudaFuncSetAttribute(attn, cudaFuncAttributeMaxDynamicSharedMemorySize, SMEM_TOTAL);

    transpose_W<<<dim3(FF / 32, FF / 32), 256>>>(W);
    gemm_Wh<<<(BB * NN) / 64, 256>>>(h, a);
    attn<<<dim3(NN / 64, BB), 256, SMEM_TOTAL>>>(adj, out);
}